// round 11
// baseline (speedup 1.0000x reference)
#include <cuda_runtime.h>

#define MAX_NODES 100000
#define EMB 128

// ---- device scratch (no dynamic allocation allowed) ----
__device__ float g_neigh[(size_t)MAX_NODES * EMB];   // 51.2 MB
__device__ int   g_deg[MAX_NODES];
__device__ float g_invdeg[MAX_NODES];
__device__ float g_WT[EMB * EMB];                    // WT[d*128+e] = W[e*128+d]

// Zero neigh accumulator + degree counters (grid-strided).
__global__ void k_zero(int n4, int nN) {
    int stride = gridDim.x * blockDim.x;
    int i = blockIdx.x * blockDim.x + threadIdx.x;
    float4 z = make_float4(0.f, 0.f, 0.f, 0.f);
    float4* p = reinterpret_cast<float4*>(g_neigh);
    for (int j = i; j < n4; j += stride) p[j] = z;
    for (int j = i; j < nN; j += stride) g_deg[j] = 0;
}

// deg[i] = #edges with src == i
__global__ void k_deg(const int* __restrict__ ei, int E) {
    int i = blockIdx.x * blockDim.x + threadIdx.x;
    if (i < E) atomicAdd(&g_deg[ei[i]], 1);
}

// invdeg = 1 / max(deg, 1); also transpose W into g_WT (both tiny).
__global__ void k_prep(const float* __restrict__ W, int nN) {
    int i = blockIdx.x * blockDim.x + threadIdx.x;
    if (i < nN) {
        int d = g_deg[i];
        g_invdeg[i] = 1.0f / (float)(d > 0 ? d : 1);
    }
    if (i < EMB * EMB) {
        int e = i & (EMB - 1);
        int d = i >> 7;
        g_WT[i] = W[e * EMB + d];   // WT[d][e] = W[e][d]
    }
}

// One warp per edge: neigh[src*128 + 4*lane .. +3] += x[dst] * invdeg[dst]
__global__ void k_scatter(const float4* __restrict__ x4,
                          const int* __restrict__ ei, int E) {
    int gtid = blockIdx.x * blockDim.x + threadIdx.x;
    int e = gtid >> 5;
    if (e >= E) return;
    int lane = threadIdx.x & 31;

    int src = __ldg(&ei[e]);
    int dst = __ldg(&ei[E + e]);
    float s = __ldg(&g_invdeg[dst]);

    float4 v = __ldg(&x4[(size_t)dst * 32 + lane]);
    v.x *= s; v.y *= s; v.z *= s; v.w *= s;

    float* p = &g_neigh[(size_t)src * EMB + lane * 4];
    asm volatile("red.global.add.v4.f32 [%0], {%1,%2,%3,%4};"
                 :: "l"(p), "f"(v.x), "f"(v.y), "f"(v.z), "f"(v.w)
                 : "memory");
}

// Fused: h = x + neigh @ W^T + b ; out = LayerNorm(h) * gamma + beta
// Each warp processes 8 full node rows; lane l owns outputs e = 4l..4l+3.
__global__ void __launch_bounds__(256, 4)
k_out(const float4* __restrict__ x4,
      const float* __restrict__ b,
      const float* __restrict__ gamma,
      const float* __restrict__ beta,
      float* __restrict__ out, int nN) {
    int warp = threadIdx.x >> 5;
    int lane = threadIdx.x & 31;
    int node0 = blockIdx.x * 64 + warp * 8;
    if (node0 >= nN) return;

    const float4* WT4  = reinterpret_cast<const float4*>(g_WT);
    const float4* ngh4 = reinterpret_cast<const float4*>(g_neigh);

    float4 acc[8];
#pragma unroll
    for (int n = 0; n < 8; n++) acc[n] = make_float4(0.f, 0.f, 0.f, 0.f);

    int nclamp = nN - 1;

#pragma unroll 4
    for (int c = 0; c < 32; c++) {       // c = d-chunk of 4
        float4 w0 = __ldg(&WT4[(4 * c + 0) * 32 + lane]);
        float4 w1 = __ldg(&WT4[(4 * c + 1) * 32 + lane]);
        float4 w2 = __ldg(&WT4[(4 * c + 2) * 32 + lane]);
        float4 w3 = __ldg(&WT4[(4 * c + 3) * 32 + lane]);
#pragma unroll
        for (int n = 0; n < 8; n++) {
            int node = node0 + n;
            node = node > nclamp ? nclamp : node;   // harmless redundant work at tail
            float4 nb = __ldg(&ngh4[(size_t)node * 32 + c]);
            acc[n].x += nb.x * w0.x + nb.y * w1.x + nb.z * w2.x + nb.w * w3.x;
            acc[n].y += nb.x * w0.y + nb.y * w1.y + nb.z * w2.y + nb.w * w3.y;
            acc[n].z += nb.x * w0.z + nb.y * w1.z + nb.z * w2.z + nb.w * w3.z;
            acc[n].w += nb.x * w0.w + nb.y * w1.w + nb.z * w2.w + nb.w * w3.w;
        }
    }

    const float4* b4  = reinterpret_cast<const float4*>(b);
    const float4* g4  = reinterpret_cast<const float4*>(gamma);
    const float4* be4 = reinterpret_cast<const float4*>(beta);
    float4 bv = __ldg(&b4[lane]);
    float4 gv = __ldg(&g4[lane]);
    float4 bt = __ldg(&be4[lane]);
    float4* out4 = reinterpret_cast<float4*>(out);

#pragma unroll
    for (int n = 0; n < 8; n++) {
        int node = node0 + n;
        if (node >= nN) break;
        float4 h = acc[n];
        float4 xv = __ldg(&x4[(size_t)node * 32 + lane]);
        h.x += xv.x + bv.x;
        h.y += xv.y + bv.y;
        h.z += xv.z + bv.z;
        h.w += xv.w + bv.w;

        float s  = h.x + h.y + h.z + h.w;
        float ss = h.x * h.x + h.y * h.y + h.z * h.z + h.w * h.w;
#pragma unroll
        for (int o = 16; o > 0; o >>= 1) {
            s  += __shfl_xor_sync(0xFFFFFFFFu, s,  o);
            ss += __shfl_xor_sync(0xFFFFFFFFu, ss, o);
        }
        float mean = s * (1.0f / 128.0f);
        float var  = ss * (1.0f / 128.0f) - mean * mean;
        float inv  = rsqrtf(var + 1e-5f);

        float4 o4;
        o4.x = (h.x - mean) * inv * gv.x + bt.x;
        o4.y = (h.y - mean) * inv * gv.y + bt.y;
        o4.z = (h.z - mean) * inv * gv.z + bt.z;
        o4.w = (h.w - mean) * inv * gv.w + bt.w;
        out4[(size_t)node * 32 + lane] = o4;
    }
}

extern "C" void kernel_launch(void* const* d_in, const int* in_sizes, int n_in,
                              void* d_out, int out_size) {
    const float* x     = (const float*)d_in[0];
    const float* W     = (const float*)d_in[1];
    const float* b     = (const float*)d_in[2];
    const float* gamma = (const float*)d_in[3];
    const float* beta  = (const float*)d_in[4];
    const int*   ei    = (const int*)d_in[5];
    float* out = (float*)d_out;

    int nN = in_sizes[0] / EMB;   // batch = 1
    int E  = in_sizes[5] / 2;

    k_zero<<<2048, 256>>>(nN * 32, nN);
    k_deg<<<(E + 255) / 256, 256>>>(ei, E);
    k_prep<<<(nN + 255) / 256, 256>>>(W, nN);
    k_scatter<<<(E * 32 + 255) / 256, 256>>>((const float4*)x, ei, E);
    k_out<<<(nN + 63) / 64, 256>>>((const float4*)x, b, gamma, beta, out, nN);
}

// round 15
// speedup vs baseline: 1.5402x; 1.5402x over previous
#include <cuda_runtime.h>

#define MAX_NODES 100000
#define EMB 128

typedef unsigned long long u64;

// ---- device scratch (no dynamic allocation allowed) ----
__device__ float g_neigh[(size_t)MAX_NODES * EMB];   // 51.2 MB
__device__ int   g_deg[MAX_NODES];
__device__ float g_invdeg[MAX_NODES];
__device__ float g_WT[EMB * EMB];                    // WT[d*128+e] = W[e*128+d]

// ---- packed f32x2 helpers (Blackwell FFMA2 path) ----
__device__ __forceinline__ u64 pack2(float a, float b) {
    u64 r; asm("mov.b64 %0, {%1, %2};" : "=l"(r) : "f"(a), "f"(b)); return r;
}
__device__ __forceinline__ void unpack2(u64 v, float& a, float& b) {
    asm("mov.b64 {%0, %1}, %2;" : "=f"(a), "=f"(b) : "l"(v));
}
__device__ __forceinline__ u64 fma2(u64 a, u64 b, u64 c) {
    u64 d; asm("fma.rn.f32x2 %0, %1, %2, %3;" : "=l"(d) : "l"(a), "l"(b), "l"(c)); return d;
}

// Zero neigh accumulator + degree counters (grid-strided).
__global__ void k_zero(int n4, int nN) {
    int stride = gridDim.x * blockDim.x;
    int i = blockIdx.x * blockDim.x + threadIdx.x;
    float4 z = make_float4(0.f, 0.f, 0.f, 0.f);
    float4* p = reinterpret_cast<float4*>(g_neigh);
    for (int j = i; j < n4; j += stride) p[j] = z;
    for (int j = i; j < nN; j += stride) g_deg[j] = 0;
}

// deg[i] = #edges with src == i
__global__ void k_deg(const int* __restrict__ ei, int E) {
    int i = blockIdx.x * blockDim.x + threadIdx.x;
    if (i < E) atomicAdd(&g_deg[ei[i]], 1);
}

// invdeg = 1 / max(deg, 1); also transpose W into g_WT (both tiny).
__global__ void k_prep(const float* __restrict__ W, int nN) {
    int i = blockIdx.x * blockDim.x + threadIdx.x;
    if (i < nN) {
        int d = g_deg[i];
        g_invdeg[i] = 1.0f / (float)(d > 0 ? d : 1);
    }
    if (i < EMB * EMB) {
        int e = i & (EMB - 1);
        int d = i >> 7;
        g_WT[i] = W[e * EMB + d];   // WT[d][e] = W[e][d]
    }
}

// 4 edges per warp: issue 4 independent gathers, then 4 vector reductions.
// MLP per warp = 4 on the dominant x[dst] gather (was 1).
__global__ void k_scatter(const float4* __restrict__ x4,
                          const int* __restrict__ ei, int E) {
    int wglobal = (blockIdx.x * blockDim.x + threadIdx.x) >> 5;
    int lane = threadIdx.x & 31;
    int e0 = wglobal * 4;
    if (e0 >= E) return;

    int src[4], dst[4];
    float iv[4];
    float4 v[4];

#pragma unroll
    for (int i = 0; i < 4; i++) {
        int e = e0 + i;
        e = e < E ? e : E - 1;              // clamp; tail edges skipped at red
        src[i] = __ldg(&ei[e]);
        dst[i] = __ldg(&ei[E + e]);
    }
#pragma unroll
    for (int i = 0; i < 4; i++) iv[i] = __ldg(&g_invdeg[dst[i]]);
#pragma unroll
    for (int i = 0; i < 4; i++) v[i] = __ldg(&x4[(size_t)dst[i] * 32 + lane]);

#pragma unroll
    for (int i = 0; i < 4; i++) {
        if (e0 + i >= E) break;
        float s = iv[i];
        float4 t = v[i];
        t.x *= s; t.y *= s; t.z *= s; t.w *= s;
        float* p = &g_neigh[(size_t)src[i] * EMB + lane * 4];
        asm volatile("red.global.add.v4.f32 [%0], {%1,%2,%3,%4};"
                     :: "l"(p), "f"(t.x), "f"(t.y), "f"(t.z), "f"(t.w)
                     : "memory");
    }
}

// Fused: h = x + neigh @ W^T + b ; out = LayerNorm(h) * gamma + beta
// Each warp processes 8 node rows; lane l owns outputs e = 4l..4l+3.
// Inner product runs on packed f32x2 FMA (FFMA2): acc pairs (e0,e1),(e2,e3).
__global__ void __launch_bounds__(256, 2)
k_out(const float4* __restrict__ x4,
      const float* __restrict__ b,
      const float* __restrict__ gamma,
      const float* __restrict__ beta,
      float* __restrict__ out, int nN) {
    int warp = threadIdx.x >> 5;
    int lane = threadIdx.x & 31;
    int node0 = blockIdx.x * 64 + warp * 8;
    if (node0 >= nN) return;

    const float4* WT4  = reinterpret_cast<const float4*>(g_WT);
    const float4* ngh4 = reinterpret_cast<const float4*>(g_neigh);

    u64 acc01[8], acc23[8];
#pragma unroll
    for (int n = 0; n < 8; n++) { acc01[n] = 0ull; acc23[n] = 0ull; }

    int nclamp = nN - 1;

#pragma unroll 2
    for (int c = 0; c < 32; c++) {       // c = d-chunk of 4
        float4 w0 = __ldg(&WT4[(4 * c + 0) * 32 + lane]);
        float4 w1 = __ldg(&WT4[(4 * c + 1) * 32 + lane]);
        float4 w2 = __ldg(&WT4[(4 * c + 2) * 32 + lane]);
        float4 w3 = __ldg(&WT4[(4 * c + 3) * 32 + lane]);
        u64 w0a = pack2(w0.x, w0.y), w0b = pack2(w0.z, w0.w);
        u64 w1a = pack2(w1.x, w1.y), w1b = pack2(w1.z, w1.w);
        u64 w2a = pack2(w2.x, w2.y), w2b = pack2(w2.z, w2.w);
        u64 w3a = pack2(w3.x, w3.y), w3b = pack2(w3.z, w3.w);
#pragma unroll
        for (int n = 0; n < 8; n++) {
            int node = node0 + n;
            node = node > nclamp ? nclamp : node;   // harmless redundant work at tail
            float4 nb = __ldg(&ngh4[(size_t)node * 32 + c]);
            u64 b0 = pack2(nb.x, nb.x);
            u64 b1 = pack2(nb.y, nb.y);
            u64 b2 = pack2(nb.z, nb.z);
            u64 b3 = pack2(nb.w, nb.w);
            acc01[n] = fma2(b0, w0a, acc01[n]);  acc23[n] = fma2(b0, w0b, acc23[n]);
            acc01[n] = fma2(b1, w1a, acc01[n]);  acc23[n] = fma2(b1, w1b, acc23[n]);
            acc01[n] = fma2(b2, w2a, acc01[n]);  acc23[n] = fma2(b2, w2b, acc23[n]);
            acc01[n] = fma2(b3, w3a, acc01[n]);  acc23[n] = fma2(b3, w3b, acc23[n]);
        }
    }

    const float4* b4  = reinterpret_cast<const float4*>(b);
    const float4* g4  = reinterpret_cast<const float4*>(gamma);
    const float4* be4 = reinterpret_cast<const float4*>(beta);
    float4 bv = __ldg(&b4[lane]);
    float4 gv = __ldg(&g4[lane]);
    float4 bt = __ldg(&be4[lane]);
    float4* out4 = reinterpret_cast<float4*>(out);

#pragma unroll
    for (int n = 0; n < 8; n++) {
        int node = node0 + n;
        if (node >= nN) break;
        float4 h;
        unpack2(acc01[n], h.x, h.y);
        unpack2(acc23[n], h.z, h.w);
        float4 xv = __ldg(&x4[(size_t)node * 32 + lane]);
        h.x += xv.x + bv.x;
        h.y += xv.y + bv.y;
        h.z += xv.z + bv.z;
        h.w += xv.w + bv.w;

        float s  = h.x + h.y + h.z + h.w;
        float ss = h.x * h.x + h.y * h.y + h.z * h.z + h.w * h.w;
#pragma unroll
        for (int o = 16; o > 0; o >>= 1) {
            s  += __shfl_xor_sync(0xFFFFFFFFu, s,  o);
            ss += __shfl_xor_sync(0xFFFFFFFFu, ss, o);
        }
        float mean = s * (1.0f / 128.0f);
        float var  = ss * (1.0f / 128.0f) - mean * mean;
        float inv  = rsqrtf(var + 1e-5f);

        float4 o4;
        o4.x = (h.x - mean) * inv * gv.x + bt.x;
        o4.y = (h.y - mean) * inv * gv.y + bt.y;
        o4.z = (h.z - mean) * inv * gv.z + bt.z;
        o4.w = (h.w - mean) * inv * gv.w + bt.w;
        out4[(size_t)node * 32 + lane] = o4;
    }
}

extern "C" void kernel_launch(void* const* d_in, const int* in_sizes, int n_in,
                              void* d_out, int out_size) {
    const float* x     = (const float*)d_in[0];
    const float* W     = (const float*)d_in[1];
    const float* b     = (const float*)d_in[2];
    const float* gamma = (const float*)d_in[3];
    const float* beta  = (const float*)d_in[4];
    const int*   ei    = (const int*)d_in[5];
    float* out = (float*)d_out;

    int nN = in_sizes[0] / EMB;   // batch = 1
    int E  = in_sizes[5] / 2;

    // 4 edges per warp -> warps = ceil(E/4); 8 warps per block -> 32 edges/block
    int scatter_blocks = (E + 31) / 32;

    k_zero<<<2048, 256>>>(nN * 32, nN);
    k_deg<<<(E + 255) / 256, 256>>>(ei, E);
    k_prep<<<(nN + 255) / 256, 256>>>(W, nN);
    k_scatter<<<scatter_blocks, 256>>>((const float4*)x, ei, E);
    k_out<<<(nN + 63) / 64, 256>>>((const float4*)x, b, gamma, beta, out, nN);
}